// round 11
// baseline (speedup 1.0000x reference)
#include <cuda_runtime.h>
#include <cuda_fp16.h>
#include <cstdint>

#define Bq   8
#define Sq   1024
#define HIDq 1024
#define NHq  16
#define HDq  64
#define Mq   (Bq * Sq)   // 8192

// Scratch (device globals: allocation-free per harness rules)
__device__ __half g_xh[(size_t)Mq * HIDq];     // A operand fp16 [M,K] (x, later ctx)
__device__ __half g_wt4[(size_t)4 * HIDq * HIDq];  // W^T fp16 [4][N,K] (q,k,v,p)
__device__ __half g_qh[(size_t)Bq * NHq * Sq * HDq];  // [B,NH,S,HD] (pre-scaled)
__device__ __half g_kh[(size_t)Bq * NHq * Sq * HDq];
__device__ __half g_vh[(size_t)Bq * NHq * Sq * HDq];

// ===========================================================================
// PTX helpers (portable tensor ISA: ldmatrix + mma.sync, sm_80+)
// ===========================================================================
__device__ __forceinline__ uint32_t smem_to_u32(const void* p) {
    uint32_t a;
    asm("{ .reg .u64 t; cvta.to.shared.u64 t, %1; cvt.u32.u64 %0, t; }"
        : "=r"(a) : "l"(p));
    return a;
}

#define LDMX4(r, addr) \
    asm volatile("ldmatrix.sync.aligned.m8n8.x4.shared.b16 {%0,%1,%2,%3}, [%4];" \
        : "=r"((r)[0]), "=r"((r)[1]), "=r"((r)[2]), "=r"((r)[3]) : "r"(addr))

#define LDMX2(r, addr) \
    asm volatile("ldmatrix.sync.aligned.m8n8.x2.shared.b16 {%0,%1}, [%2];" \
        : "=r"((r)[0]), "=r"((r)[1]) : "r"(addr))

#define LDMX2T(r, addr) \
    asm volatile("ldmatrix.sync.aligned.m8n8.x2.trans.shared.b16 {%0,%1}, [%2];" \
        : "=r"((r)[0]), "=r"((r)[1]) : "r"(addr))

#define MMA_F16(d, a, b) \
    asm volatile("mma.sync.aligned.m16n8k16.row.col.f32.f16.f16.f32 " \
        "{%0,%1,%2,%3}, {%4,%5,%6,%7}, {%8,%9}, {%0,%1,%2,%3};" \
        : "+f"((d)[0]), "+f"((d)[1]), "+f"((d)[2]), "+f"((d)[3]) \
        : "r"((a)[0]), "r"((a)[1]), "r"((a)[2]), "r"((a)[3]), \
          "r"((b)[0]), "r"((b)[1]))

#define CP_ASYNC16(smem, gmem) \
    asm volatile("cp.async.cg.shared.global [%0], [%1], 16;" \
        :: "r"(smem), "l"(gmem) : "memory")
#define CP_COMMIT()  asm volatile("cp.async.commit_group;" ::: "memory")
#define CP_WAIT(n)   asm volatile("cp.async.wait_group %0;" :: "n"(n) : "memory")

// ===========================================================================
// Conversion: x fp32 -> fp16
// ===========================================================================
__global__ __launch_bounds__(256) void convert_x_kernel(const float* __restrict__ src)
{
    const size_t i = ((size_t)blockIdx.x * 256 + threadIdx.x) * 8;
    float4 v0 = *(const float4*)(src + i);
    float4 v1 = *(const float4*)(src + i + 4);
    __half2 h0 = __floats2half2_rn(v0.x, v0.y);
    __half2 h1 = __floats2half2_rn(v0.z, v0.w);
    __half2 h2 = __floats2half2_rn(v1.x, v1.y);
    __half2 h3 = __floats2half2_rn(v1.z, v1.w);
    *(uint4*)(g_xh + i) = make_uint4(*(uint32_t*)&h0, *(uint32_t*)&h1,
                                     *(uint32_t*)&h2, *(uint32_t*)&h3);
}

// ===========================================================================
// All-weights transpose: g_wt4[z][n][k] = fp16(Wz[k][n]) for z in {q,k,v,p}
// ===========================================================================
__global__ __launch_bounds__(256) void convw_all_kernel(
    const float* __restrict__ W0, const float* __restrict__ W1,
    const float* __restrict__ W2, const float* __restrict__ W3)
{
    __shared__ float tile[32][33];
    const float* W = (blockIdx.z == 0) ? W0 : (blockIdx.z == 1) ? W1
                   : (blockIdx.z == 2) ? W2 : W3;
    __half* dst = g_wt4 + (size_t)blockIdx.z * HIDq * HIDq;
    const int bx = blockIdx.x * 32, by = blockIdx.y * 32;
    const int tx = threadIdx.x & 31, ty = threadIdx.x >> 5;  // 32 x 8
#pragma unroll
    for (int i = 0; i < 4; i++)
        tile[ty + i * 8][tx] = W[(size_t)(by + ty + i * 8) * HIDq + bx + tx];
    __syncthreads();
#pragma unroll
    for (int i = 0; i < 4; i++)
        dst[(size_t)(bx + ty + i * 8) * HIDq + by + tx] =
            __float2half(tile[tx][ty + i * 8]);
}

// ===========================================================================
// fp16 mma.sync GEMM core. KCH=64 (16 chunks), 2-stage cp.async pipeline.
// CTA 128x128, 8 warps (2m x 4n). Row stride 144 B (conflict-free).
// ===========================================================================
#define KCH    64
#define GTILE  18432                    // 128 rows x 144 B
#define GSTG   (2 * GTILE)              // A + B per stage
#define GSMEM  (2 * GSTG)               // 73728 B, 2 stages

// QKV merged GEMM: z = blockIdx.z selects weight slot, bias, destination.
__global__ __launch_bounds__(256, 2) void gemm_qkv_kernel(
    const float* __restrict__ b0, const float* __restrict__ b1,
    const float* __restrict__ b2)
{
    extern __shared__ char sm[];
    const uint32_t sb = smem_to_u32(sm);
    const int z = blockIdx.z;
    const __half* Wt = g_wt4 + (size_t)z * HIDq * HIDq;
    const float* bias = (z == 0) ? b0 : (z == 1) ? b1 : b2;
    __half* dst = (z == 0) ? g_qh : (z == 1) ? g_kh : g_vh;

    const int tid = threadIdx.x, lane = tid & 31, wid = tid >> 5;
    const int wm = wid >> 2, wn = wid & 3;
    const int bm = blockIdx.y * 128, bn = blockIdx.x * 128;

    float acc[4][4][4];
#pragma unroll
    for (int mi = 0; mi < 4; mi++)
#pragma unroll
        for (int ni = 0; ni < 4; ni++)
#pragma unroll
            for (int r = 0; r < 4; r++) acc[mi][ni][r] = 0.f;

    auto issue = [&](int c) {
        const uint32_t base = sb + (uint32_t)(c & 1) * GSTG;
        const int k0 = c * KCH;
#pragma unroll
        for (int t = 0; t < 4; t++) {
            const int id = t * 256 + tid;
            const int row = id >> 3, seg = id & 7;
            const uint32_t so = (uint32_t)row * 144 + seg * 16;
            CP_ASYNC16(base + so,         g_xh + (size_t)(bm + row) * HIDq + k0 + seg * 8);
            CP_ASYNC16(base + GTILE + so, Wt   + (size_t)(bn + row) * HIDq + k0 + seg * 8);
        }
        CP_COMMIT();
    };

    issue(0);

    for (int c = 0; c < HIDq / KCH; c++) {
        if (c + 1 < HIDq / KCH) { issue(c + 1); CP_WAIT(1); }
        else                    { CP_WAIT(0); }
        __syncthreads();

        const uint32_t base = sb + (uint32_t)(c & 1) * GSTG;

#pragma unroll
        for (int kk = 0; kk < KCH; kk += 16) {
            uint32_t bh[4][2];
#pragma unroll
            for (int ni = 0; ni < 4; ni++) {
                const uint32_t baddr = base + GTILE
                    + (uint32_t)(wn * 32 + ni * 8 + (lane & 7)) * 144
                    + (uint32_t)(kk + ((lane >> 3) & 1) * 8) * 2;
                LDMX2(bh[ni], baddr);
            }
#pragma unroll
            for (int mi = 0; mi < 4; mi++) {
                const uint32_t aaddr = base
                    + (uint32_t)(wm * 64 + mi * 16 + (lane & 15)) * 144
                    + (uint32_t)(kk + (lane >> 4) * 8) * 2;
                uint32_t ah[4];
                LDMX4(ah, aaddr);
#pragma unroll
                for (int ni = 0; ni < 4; ni++)
                    MMA_F16(acc[mi][ni], ah, bh[ni]);
            }
        }
        __syncthreads();
    }

    const int rbase = bm + wm * 64 + (lane >> 2);
    const int cbase = bn + wn * 32 + (lane & 3) * 2;
    const float qs = (z == 0) ? 0.03125f : 1.0f;
#pragma unroll
    for (int mi = 0; mi < 4; mi++) {
#pragma unroll
        for (int ni = 0; ni < 4; ni++) {
            const int col = cbase + ni * 8;
            const float2 b2v = *(const float2*)(bias + col);
#pragma unroll
            for (int half = 0; half < 2; half++) {
                const int row = rbase + mi * 16 + half * 8;
                const float ox = (acc[mi][ni][half * 2 + 0] + b2v.x) * qs;
                const float oy = (acc[mi][ni][half * 2 + 1] + b2v.y) * qs;
                const int b = row >> 10, s = row & 1023;
                const int h = col >> 6,  d = col & 63;
                const size_t off = (((size_t)(b * NHq + h)) * Sq + s) * HDq + d;
                __half2 h2 = __floats2half2_rn(ox, oy);
                *(uint32_t*)(dst + off) = *(uint32_t*)&h2;
            }
        }
    }
}

// Output projection: A = g_xh (ctx), W slot 3, fp32 row-major to d_out.
__global__ __launch_bounds__(256, 2) void gemm_out_kernel(
    const float* __restrict__ bias, float* __restrict__ Cout)
{
    extern __shared__ char sm[];
    const uint32_t sb = smem_to_u32(sm);
    const __half* Wt = g_wt4 + (size_t)3 * HIDq * HIDq;

    const int tid = threadIdx.x, lane = tid & 31, wid = tid >> 5;
    const int wm = wid >> 2, wn = wid & 3;
    const int bm = blockIdx.y * 128, bn = blockIdx.x * 128;

    float acc[4][4][4];
#pragma unroll
    for (int mi = 0; mi < 4; mi++)
#pragma unroll
        for (int ni = 0; ni < 4; ni++)
#pragma unroll
            for (int r = 0; r < 4; r++) acc[mi][ni][r] = 0.f;

    auto issue = [&](int c) {
        const uint32_t base = sb + (uint32_t)(c & 1) * GSTG;
        const int k0 = c * KCH;
#pragma unroll
        for (int t = 0; t < 4; t++) {
            const int id = t * 256 + tid;
            const int row = id >> 3, seg = id & 7;
            const uint32_t so = (uint32_t)row * 144 + seg * 16;
            CP_ASYNC16(base + so,         g_xh + (size_t)(bm + row) * HIDq + k0 + seg * 8);
            CP_ASYNC16(base + GTILE + so, Wt   + (size_t)(bn + row) * HIDq + k0 + seg * 8);
        }
        CP_COMMIT();
    };

    issue(0);

    for (int c = 0; c < HIDq / KCH; c++) {
        if (c + 1 < HIDq / KCH) { issue(c + 1); CP_WAIT(1); }
        else                    { CP_WAIT(0); }
        __syncthreads();

        const uint32_t base = sb + (uint32_t)(c & 1) * GSTG;

#pragma unroll
        for (int kk = 0; kk < KCH; kk += 16) {
            uint32_t bh[4][2];
#pragma unroll
            for (int ni = 0; ni < 4; ni++) {
                const uint32_t baddr = base + GTILE
                    + (uint32_t)(wn * 32 + ni * 8 + (lane & 7)) * 144
                    + (uint32_t)(kk + ((lane >> 3) & 1) * 8) * 2;
                LDMX2(bh[ni], baddr);
            }
#pragma unroll
            for (int mi = 0; mi < 4; mi++) {
                const uint32_t aaddr = base
                    + (uint32_t)(wm * 64 + mi * 16 + (lane & 15)) * 144
                    + (uint32_t)(kk + (lane >> 4) * 8) * 2;
                uint32_t ah[4];
                LDMX4(ah, aaddr);
#pragma unroll
                for (int ni = 0; ni < 4; ni++)
                    MMA_F16(acc[mi][ni], ah, bh[ni]);
            }
        }
        __syncthreads();
    }

    const int rbase = bm + wm * 64 + (lane >> 2);
    const int cbase = bn + wn * 32 + (lane & 3) * 2;
#pragma unroll
    for (int mi = 0; mi < 4; mi++) {
#pragma unroll
        for (int ni = 0; ni < 4; ni++) {
            const int col = cbase + ni * 8;
            const float2 b2v = *(const float2*)(bias + col);
#pragma unroll
            for (int half = 0; half < 2; half++) {
                const int row = rbase + mi * 16 + half * 8;
                *(float2*)(Cout + (size_t)row * HIDq + col) =
                    make_float2(acc[mi][ni][half * 2 + 0] + b2v.x,
                                acc[mi][ni][half * 2 + 1] + b2v.y);
            }
        }
    }
}

// ===========================================================================
// fp16 flash attention v2: 128 threads = 4 warps, warp owns 32 query rows
// (2 m-tiles). K/V fragments loaded ONCE per warp, reused for both m-tiles;
// Q fragments hoisted to registers. 128-query tile, 64-key stages (2-stage).
// ctx -> fp16 into g_xh [B*S, HID].
// ===========================================================================
#define QTILE  18432                    // 128 rows x 144 B
#define KVTILE 9216                     // 64 rows x 144 B
#define KVSTG  (2 * KVTILE)             // Kh, Vh
#define KVOFF  QTILE
#define ASMEM  (KVOFF + 2 * KVSTG)      // 55296
#define NTK    (Sq / 64)                // 16

__global__ __launch_bounds__(128, 2) void attn_mma_kernel(const float* __restrict__ mask)
{
    extern __shared__ char sm[];
    const uint32_t sb = smem_to_u32(sm);

    const int bh = blockIdx.y;
    const int b = bh >> 4, h = bh & 15;
    const int qbase = blockIdx.x * 128;
    const int tid = threadIdx.x, lane = tid & 31, wid = tid >> 5;  // 4 warps
    const int wrow = wid * 32;

    const size_t hb = (size_t)bh * Sq * HDq;
    const __half* Qg = g_qh + hb;
    const __half* KVg[2] = {g_kh + hb, g_vh + hb};

    // Q load (group 0 together with KV stage 0): 1024 segs / 128 thr = 8
#pragma unroll
    for (int t = 0; t < 8; t++) {
        const int id = t * 128 + tid;
        const int row = id >> 3, seg = id & 7;
        CP_ASYNC16(sb + (uint32_t)row * 144 + seg * 16,
                   Qg + (size_t)(qbase + row) * HDq + seg * 8);
    }

    auto issue_kv = [&](int kt) {
        const uint32_t base = sb + KVOFF + (uint32_t)(kt & 1) * KVSTG;
#pragma unroll
        for (int t = 0; t < 8; t++) {
            const int which = t >> 2;           // 0=Kh, 1=Vh
            const int id = (t & 3) * 128 + tid;
            const int row = id >> 3, seg = id & 7;
            CP_ASYNC16(base + (uint32_t)which * KVTILE + (uint32_t)row * 144 + seg * 16,
                       KVg[which] + (size_t)(kt * 64 + row) * HDq + seg * 8);
        }
        CP_COMMIT();
    };

    issue_kv(0);

    float m_st[2][2], l_st[2][2];
    float ctx[2][8][4];
#pragma unroll
    for (int mi = 0; mi < 2; mi++) {
        m_st[mi][0] = m_st[mi][1] = -1e30f;
        l_st[mi][0] = l_st[mi][1] = 0.f;
#pragma unroll
        for (int n = 0; n < 8; n++)
#pragma unroll
            for (int r = 0; r < 4; r++) ctx[mi][n][r] = 0.f;
    }

    uint32_t ah[2][4][4];   // Q fragments, hoisted (mi, k0-group)

    for (int kt = 0; kt < NTK; kt++) {
        if (kt + 1 < NTK) { issue_kv(kt + 1); CP_WAIT(1); }
        else              { CP_WAIT(0); }
        __syncthreads();

        if (kt == 0) {
#pragma unroll
            for (int mi = 0; mi < 2; mi++)
#pragma unroll
                for (int kq = 0; kq < 4; kq++) {
                    const uint32_t aaddr = sb
                        + (uint32_t)(wrow + mi * 16 + (lane & 15)) * 144
                        + (uint32_t)(kq * 16 + (lane >> 4) * 8) * 2;
                    LDMX4(ah[mi][kq], aaddr);
                }
        }

        const uint32_t kvb = sb + KVOFF + (uint32_t)(kt & 1) * KVSTG;

        // ---- scores: both m-tiles share each K fragment ----
        float accs[2][8][4];
#pragma unroll
        for (int mi = 0; mi < 2; mi++)
#pragma unroll
            for (int n = 0; n < 8; n++)
#pragma unroll
                for (int r = 0; r < 4; r++) accs[mi][n][r] = 0.f;

#pragma unroll
        for (int kq = 0; kq < 4; kq++) {
#pragma unroll
            for (int n = 0; n < 8; n++) {
                const uint32_t baddr = kvb + (uint32_t)(n * 8 + (lane & 7)) * 144
                                     + (uint32_t)(kq * 16 + ((lane >> 3) & 1) * 8) * 2;
                uint32_t kb[2];
                LDMX2(kb, baddr);
                MMA_F16(accs[0][n], ah[0][kq], kb);
                MMA_F16(accs[1][n], ah[1][kq], kb);
            }
        }

        // ---- mask + online softmax + P->fp16, per m-tile ----
        uint32_t pf[2][4][4];
#pragma unroll
        for (int mi = 0; mi < 2; mi++) {
            const int r0 = qbase + wrow + mi * 16 + (lane >> 2);
            const float* mrow0 = mask + ((size_t)b * Sq + r0) * Sq + kt * 64 + (lane & 3) * 2;
            const float* mrow1 = mrow0 + 8 * Sq;
#pragma unroll
            for (int n = 0; n < 8; n++) {
                const float2 m0 = *(const float2*)(mrow0 + n * 8);
                const float2 m1 = *(const float2*)(mrow1 + n * 8);
                accs[mi][n][0] = fmaf(m0.x, -1e9f, accs[mi][n][0]);
                accs[mi][n][1] = fmaf(m0.y, -1e9f, accs[mi][n][1]);
                accs[mi][n][2] = fmaf(m1.x, -1e9f, accs[mi][n][2]);
                accs[mi][n][3] = fmaf(m1.y, -1e9f, accs[mi][n][3]);
            }

            float mx0 = -1e30f, mx1 = -1e30f;
#pragma unroll
            for (int n = 0; n < 8; n++) {
                mx0 = fmaxf(mx0, fmaxf(accs[mi][n][0], accs[mi][n][1]));
                mx1 = fmaxf(mx1, fmaxf(accs[mi][n][2], accs[mi][n][3]));
            }
            mx0 = fmaxf(mx0, __shfl_xor_sync(0xffffffffu, mx0, 1));
            mx0 = fmaxf(mx0, __shfl_xor_sync(0xffffffffu, mx0, 2));
            mx1 = fmaxf(mx1, __shfl_xor_sync(0xffffffffu, mx1, 1));
            mx1 = fmaxf(mx1, __shfl_xor_sync(0xffffffffu, mx1, 2));

            const float mn0 = fmaxf(m_st[mi][0], mx0);
            const float mn1 = fmaxf(m_st[mi][1], mx1);
            const float al0 = __expf(m_st[mi][0] - mn0);
            const float al1 = __expf(m_st[mi][1] - mn1);
            m_st[mi][0] = mn0; m_st[mi][1] = mn1;

            float sum0 = 0.f, sum1 = 0.f;
#pragma unroll
            for (int n = 0; n < 8; n++) {
                accs[mi][n][0] = __expf(accs[mi][n][0] - mn0);
                accs[mi][n][1] = __expf(accs[mi][n][1] - mn0);
                accs[mi][n][2] = __expf(accs[mi][n][2] - mn1);
                accs[mi][n][3] = __expf(accs[mi][n][3] - mn1);
                sum0 += accs[mi][n][0] + accs[mi][n][1];
                sum1 += accs[mi][n][2] + accs[mi][n][3];
            }
            sum0 += __shfl_xor_sync(0xffffffffu, sum0, 1);
            sum0 += __shfl_xor_sync(0xffffffffu, sum0, 2);
            sum1 += __shfl_xor_sync(0xffffffffu, sum1, 1);
            sum1 += __shfl_xor_sync(0xffffffffu, sum1, 2);
            l_st[mi][0] = l_st[mi][0] * al0 + sum0;
            l_st[mi][1] = l_st[mi][1] * al1 + sum1;

#pragma unroll
            for (int n = 0; n < 8; n++) {
                ctx[mi][n][0] *= al0; ctx[mi][n][1] *= al0;
                ctx[mi][n][2] *= al1; ctx[mi][n][3] *= al1;
            }

#pragma unroll
            for (int kk2 = 0; kk2 < 4; kk2++) {
                __half2 p0 = __floats2half2_rn(accs[mi][2 * kk2][0],     accs[mi][2 * kk2][1]);
                __half2 p1 = __floats2half2_rn(accs[mi][2 * kk2][2],     accs[mi][2 * kk2][3]);
                __half2 p2 = __floats2half2_rn(accs[mi][2 * kk2 + 1][0], accs[mi][2 * kk2 + 1][1]);
                __half2 p3 = __floats2half2_rn(accs[mi][2 * kk2 + 1][2], accs[mi][2 * kk2 + 1][3]);
                pf[mi][kk2][0] = *(uint32_t*)&p0;
                pf[mi][kk2][1] = *(uint32_t*)&p1;
                pf[mi][kk2][2] = *(uint32_t*)&p2;
                pf[mi][kk2][3] = *(uint32_t*)&p3;
            }
        }

        // ---- PV: both m-tiles share each V fragment ----
        const uint32_t vbase = kvb + KVTILE;
#pragma unroll
        for (int kk2 = 0; kk2 < 4; kk2++) {
#pragma unroll
            for (int n = 0; n < 8; n++) {
                const uint32_t vaddr = vbase + (uint32_t)(kk2 * 16 + (lane & 15)) * 144
                                     + (uint32_t)n * 16;
                uint32_t vh[2];
                LDMX2T(vh, vaddr);
                MMA_F16(ctx[0][n], pf[0][kk2], vh);
                MMA_F16(ctx[1][n], pf[1][kk2], vh);
            }
        }
        __syncthreads();
    }

    // ---- epilogue: ctx / l -> fp16 into g_xh [B*S, HID] ----
    const int cb = h * HDq + (lane & 3) * 2;
#pragma unroll
    for (int mi = 0; mi < 2; mi++) {
        const int r0 = qbase + wrow + mi * 16 + (lane >> 2);
        const float inv0 = 1.0f / l_st[mi][0];
        const float inv1 = 1.0f / l_st[mi][1];
#pragma unroll
        for (int n = 0; n < 8; n++) {
            const int col = cb + n * 8;
            const size_t off0 = ((size_t)(b * Sq + r0)) * HIDq + col;
            const size_t off1 = ((size_t)(b * Sq + r0 + 8)) * HIDq + col;
            __half2 h0 = __floats2half2_rn(ctx[mi][n][0] * inv0, ctx[mi][n][1] * inv0);
            __half2 h1 = __floats2half2_rn(ctx[mi][n][2] * inv1, ctx[mi][n][3] * inv1);
            *(uint32_t*)(g_xh + off0) = *(uint32_t*)&h0;
            *(uint32_t*)(g_xh + off1) = *(uint32_t*)&h1;
        }
    }
}

// ---------------------------------------------------------------------------
extern "C" void kernel_launch(void* const* d_in, const int* in_sizes, int n_in,
                              void* d_out, int out_size)
{
    (void)in_sizes; (void)n_in; (void)out_size;
    const float* x   = (const float*)d_in[0];
    const float* msk = (const float*)d_in[1];
    const float* Wq  = (const float*)d_in[2];
    const float* bq  = (const float*)d_in[3];
    const float* Wk  = (const float*)d_in[4];
    const float* bk  = (const float*)d_in[5];
    const float* Wv  = (const float*)d_in[6];
    const float* bv  = (const float*)d_in[7];
    const float* Wp  = (const float*)d_in[8];
    const float* bp  = (const float*)d_in[9];
    float* out = (float*)d_out;

    cudaFuncSetAttribute(gemm_qkv_kernel, cudaFuncAttributeMaxDynamicSharedMemorySize, GSMEM);
    cudaFuncSetAttribute(gemm_out_kernel, cudaFuncAttributeMaxDynamicSharedMemorySize, GSMEM);
    cudaFuncSetAttribute(attn_mma_kernel, cudaFuncAttributeMaxDynamicSharedMemorySize, ASMEM);

    convert_x_kernel<<<(Mq * HIDq) / (256 * 8), 256>>>(x);
    convw_all_kernel<<<dim3(32, 32, 4), 256>>>(Wq, Wk, Wv, Wp);

    gemm_qkv_kernel<<<dim3(HIDq / 128, Mq / 128, 3), 256, GSMEM>>>(bq, bk, bv);

    attn_mma_kernel<<<dim3(Sq / 128, Bq * NHq), 128, ASMEM>>>(msk);

    gemm_out_kernel<<<dim3(HIDq / 128, Mq / 128), 256, GSMEM>>>(bp, out);
}

// round 12
// speedup vs baseline: 1.0647x; 1.0647x over previous
#include <cuda_runtime.h>
#include <cuda_fp16.h>
#include <cstdint>

#define Bq   8
#define Sq   1024
#define HIDq 1024
#define NHq  16
#define HDq  64
#define Mq   (Bq * Sq)   // 8192

// Scratch (device globals: allocation-free per harness rules)
__device__ __half g_xh[(size_t)Mq * HIDq];     // A operand fp16 [M,K] (x, later ctx)
__device__ __half g_wt4[(size_t)4 * HIDq * HIDq];  // W^T fp16 [4][N,K] (q,k,v,p)
__device__ __half g_qh[(size_t)Bq * NHq * Sq * HDq];  // [B,NH,S,HD] (pre-scaled)
__device__ __half g_kh[(size_t)Bq * NHq * Sq * HDq];
__device__ __half g_vh[(size_t)Bq * NHq * Sq * HDq];

// ===========================================================================
// PTX helpers (portable tensor ISA: ldmatrix + mma.sync, sm_80+)
// ===========================================================================
__device__ __forceinline__ uint32_t smem_to_u32(const void* p) {
    uint32_t a;
    asm("{ .reg .u64 t; cvta.to.shared.u64 t, %1; cvt.u32.u64 %0, t; }"
        : "=r"(a) : "l"(p));
    return a;
}

#define LDMX4(r, addr) \
    asm volatile("ldmatrix.sync.aligned.m8n8.x4.shared.b16 {%0,%1,%2,%3}, [%4];" \
        : "=r"((r)[0]), "=r"((r)[1]), "=r"((r)[2]), "=r"((r)[3]) : "r"(addr))

#define LDMX4T(r, addr) \
    asm volatile("ldmatrix.sync.aligned.m8n8.x4.trans.shared.b16 {%0,%1,%2,%3}, [%4];" \
        : "=r"((r)[0]), "=r"((r)[1]), "=r"((r)[2]), "=r"((r)[3]) : "r"(addr))

#define MMA_F16(d, a, b) \
    asm volatile("mma.sync.aligned.m16n8k16.row.col.f32.f16.f16.f32 " \
        "{%0,%1,%2,%3}, {%4,%5,%6,%7}, {%8,%9}, {%0,%1,%2,%3};" \
        : "+f"((d)[0]), "+f"((d)[1]), "+f"((d)[2]), "+f"((d)[3]) \
        : "r"((a)[0]), "r"((a)[1]), "r"((a)[2]), "r"((a)[3]), \
          "r"((b)[0]), "r"((b)[1]))

#define CP_ASYNC16(smem, gmem) \
    asm volatile("cp.async.cg.shared.global [%0], [%1], 16;" \
        :: "r"(smem), "l"(gmem) : "memory")
#define CP_COMMIT()  asm volatile("cp.async.commit_group;" ::: "memory")
#define CP_WAIT(n)   asm volatile("cp.async.wait_group %0;" :: "n"(n) : "memory")

// ===========================================================================
// Conversion: x fp32 -> fp16
// ===========================================================================
__global__ __launch_bounds__(256) void convert_x_kernel(const float* __restrict__ src)
{
    const size_t i = ((size_t)blockIdx.x * 256 + threadIdx.x) * 8;
    float4 v0 = *(const float4*)(src + i);
    float4 v1 = *(const float4*)(src + i + 4);
    __half2 h0 = __floats2half2_rn(v0.x, v0.y);
    __half2 h1 = __floats2half2_rn(v0.z, v0.w);
    __half2 h2 = __floats2half2_rn(v1.x, v1.y);
    __half2 h3 = __floats2half2_rn(v1.z, v1.w);
    *(uint4*)(g_xh + i) = make_uint4(*(uint32_t*)&h0, *(uint32_t*)&h1,
                                     *(uint32_t*)&h2, *(uint32_t*)&h3);
}

// ===========================================================================
// All-weights transpose: g_wt4[z][n][k] = fp16(Wz[k][n]) for z in {q,k,v,p}
// ===========================================================================
__global__ __launch_bounds__(256) void convw_all_kernel(
    const float* __restrict__ W0, const float* __restrict__ W1,
    const float* __restrict__ W2, const float* __restrict__ W3)
{
    __shared__ float tile[32][33];
    const float* W = (blockIdx.z == 0) ? W0 : (blockIdx.z == 1) ? W1
                   : (blockIdx.z == 2) ? W2 : W3;
    __half* dst = g_wt4 + (size_t)blockIdx.z * HIDq * HIDq;
    const int bx = blockIdx.x * 32, by = blockIdx.y * 32;
    const int tx = threadIdx.x & 31, ty = threadIdx.x >> 5;  // 32 x 8
#pragma unroll
    for (int i = 0; i < 4; i++)
        tile[ty + i * 8][tx] = W[(size_t)(by + ty + i * 8) * HIDq + bx + tx];
    __syncthreads();
#pragma unroll
    for (int i = 0; i < 4; i++)
        dst[(size_t)(bx + ty + i * 8) * HIDq + by + tx] =
            __float2half(tile[tx][ty + i * 8]);
}

// ===========================================================================
// fp16 mma.sync GEMM core. KCH=64 (16 chunks), 2-stage cp.async pipeline.
// CTA 128x128, 8 warps (2m x 4n). Row stride 144 B (conflict-free).
// B operand loaded with x4 ldmatrix (two 8-row n-tiles per instruction).
// ===========================================================================
#define KCH    64
#define GTILE  18432                    // 128 rows x 144 B
#define GSTG   (2 * GTILE)              // A + B per stage
#define GSMEM  (2 * GSTG)               // 73728 B, 2 stages

// QKV merged GEMM: z = blockIdx.z selects weight slot, bias, destination.
__global__ __launch_bounds__(256, 2) void gemm_qkv_kernel(
    const float* __restrict__ b0, const float* __restrict__ b1,
    const float* __restrict__ b2)
{
    extern __shared__ char sm[];
    const uint32_t sb = smem_to_u32(sm);
    const int z = blockIdx.z;
    const __half* Wt = g_wt4 + (size_t)z * HIDq * HIDq;
    const float* bias = (z == 0) ? b0 : (z == 1) ? b1 : b2;
    __half* dst = (z == 0) ? g_qh : (z == 1) ? g_kh : g_vh;

    const int tid = threadIdx.x, lane = tid & 31, wid = tid >> 5;
    const int wm = wid >> 2, wn = wid & 3;
    const int bm = blockIdx.y * 128, bn = blockIdx.x * 128;

    float acc[4][4][4];
#pragma unroll
    for (int mi = 0; mi < 4; mi++)
#pragma unroll
        for (int ni = 0; ni < 4; ni++)
#pragma unroll
            for (int r = 0; r < 4; r++) acc[mi][ni][r] = 0.f;

    auto issue = [&](int c) {
        const uint32_t base = sb + (uint32_t)(c & 1) * GSTG;
        const int k0 = c * KCH;
#pragma unroll
        for (int t = 0; t < 4; t++) {
            const int id = t * 256 + tid;
            const int row = id >> 3, seg = id & 7;
            const uint32_t so = (uint32_t)row * 144 + seg * 16;
            CP_ASYNC16(base + so,         g_xh + (size_t)(bm + row) * HIDq + k0 + seg * 8);
            CP_ASYNC16(base + GTILE + so, Wt   + (size_t)(bn + row) * HIDq + k0 + seg * 8);
        }
        CP_COMMIT();
    };

    issue(0);

    // x4 B-frag address: row = wn*32 + ni2*16 + (lane&7) + ((lane>>4)&1)*8,
    // k-half = (lane>>3)&1  ->  {r0,r1} = n-tile 2*ni2, {r2,r3} = 2*ni2+1
    const uint32_t brow = (uint32_t)(wn * 32 + (lane & 7) + ((lane >> 4) & 1) * 8);
    const uint32_t bkp  = (uint32_t)(((lane >> 3) & 1) * 8) * 2;

    for (int c = 0; c < HIDq / KCH; c++) {
        if (c + 1 < HIDq / KCH) { issue(c + 1); CP_WAIT(1); }
        else                    { CP_WAIT(0); }
        __syncthreads();

        const uint32_t base = sb + (uint32_t)(c & 1) * GSTG;

#pragma unroll
        for (int kk = 0; kk < KCH; kk += 16) {
            uint32_t bh[2][4];
#pragma unroll
            for (int ni2 = 0; ni2 < 2; ni2++) {
                const uint32_t baddr = base + GTILE
                    + (brow + (uint32_t)ni2 * 16) * 144
                    + (uint32_t)kk * 2 + bkp;
                LDMX4(bh[ni2], baddr);
            }
#pragma unroll
            for (int mi = 0; mi < 4; mi++) {
                const uint32_t aaddr = base
                    + (uint32_t)(wm * 64 + mi * 16 + (lane & 15)) * 144
                    + (uint32_t)(kk + (lane >> 4) * 8) * 2;
                uint32_t ah[4];
                LDMX4(ah, aaddr);
#pragma unroll
                for (int ni2 = 0; ni2 < 2; ni2++) {
                    MMA_F16(acc[mi][ni2 * 2 + 0], ah, bh[ni2]);
                    MMA_F16(acc[mi][ni2 * 2 + 1], ah, bh[ni2] + 2);
                }
            }
        }
        __syncthreads();
    }

    const int rbase = bm + wm * 64 + (lane >> 2);
    const int cbase = bn + wn * 32 + (lane & 3) * 2;
    const float qs = (z == 0) ? 0.03125f : 1.0f;
#pragma unroll
    for (int mi = 0; mi < 4; mi++) {
#pragma unroll
        for (int ni = 0; ni < 4; ni++) {
            const int col = cbase + ni * 8;
            const float2 b2v = *(const float2*)(bias + col);
#pragma unroll
            for (int half = 0; half < 2; half++) {
                const int row = rbase + mi * 16 + half * 8;
                const float ox = (acc[mi][ni][half * 2 + 0] + b2v.x) * qs;
                const float oy = (acc[mi][ni][half * 2 + 1] + b2v.y) * qs;
                const int b = row >> 10, s = row & 1023;
                const int h = col >> 6,  d = col & 63;
                const size_t off = (((size_t)(b * NHq + h)) * Sq + s) * HDq + d;
                __half2 h2 = __floats2half2_rn(ox, oy);
                *(uint32_t*)(dst + off) = *(uint32_t*)&h2;
            }
        }
    }
}

// Output projection: A = g_xh (ctx), W slot 3, fp32 row-major to d_out.
__global__ __launch_bounds__(256, 2) void gemm_out_kernel(
    const float* __restrict__ bias, float* __restrict__ Cout)
{
    extern __shared__ char sm[];
    const uint32_t sb = smem_to_u32(sm);
    const __half* Wt = g_wt4 + (size_t)3 * HIDq * HIDq;

    const int tid = threadIdx.x, lane = tid & 31, wid = tid >> 5;
    const int wm = wid >> 2, wn = wid & 3;
    const int bm = blockIdx.y * 128, bn = blockIdx.x * 128;

    float acc[4][4][4];
#pragma unroll
    for (int mi = 0; mi < 4; mi++)
#pragma unroll
        for (int ni = 0; ni < 4; ni++)
#pragma unroll
            for (int r = 0; r < 4; r++) acc[mi][ni][r] = 0.f;

    auto issue = [&](int c) {
        const uint32_t base = sb + (uint32_t)(c & 1) * GSTG;
        const int k0 = c * KCH;
#pragma unroll
        for (int t = 0; t < 4; t++) {
            const int id = t * 256 + tid;
            const int row = id >> 3, seg = id & 7;
            const uint32_t so = (uint32_t)row * 144 + seg * 16;
            CP_ASYNC16(base + so,         g_xh + (size_t)(bm + row) * HIDq + k0 + seg * 8);
            CP_ASYNC16(base + GTILE + so, Wt   + (size_t)(bn + row) * HIDq + k0 + seg * 8);
        }
        CP_COMMIT();
    };

    issue(0);

    const uint32_t brow = (uint32_t)(wn * 32 + (lane & 7) + ((lane >> 4) & 1) * 8);
    const uint32_t bkp  = (uint32_t)(((lane >> 3) & 1) * 8) * 2;

    for (int c = 0; c < HIDq / KCH; c++) {
        if (c + 1 < HIDq / KCH) { issue(c + 1); CP_WAIT(1); }
        else                    { CP_WAIT(0); }
        __syncthreads();

        const uint32_t base = sb + (uint32_t)(c & 1) * GSTG;

#pragma unroll
        for (int kk = 0; kk < KCH; kk += 16) {
            uint32_t bh[2][4];
#pragma unroll
            for (int ni2 = 0; ni2 < 2; ni2++) {
                const uint32_t baddr = base + GTILE
                    + (brow + (uint32_t)ni2 * 16) * 144
                    + (uint32_t)kk * 2 + bkp;
                LDMX4(bh[ni2], baddr);
            }
#pragma unroll
            for (int mi = 0; mi < 4; mi++) {
                const uint32_t aaddr = base
                    + (uint32_t)(wm * 64 + mi * 16 + (lane & 15)) * 144
                    + (uint32_t)(kk + (lane >> 4) * 8) * 2;
                uint32_t ah[4];
                LDMX4(ah, aaddr);
#pragma unroll
                for (int ni2 = 0; ni2 < 2; ni2++) {
                    MMA_F16(acc[mi][ni2 * 2 + 0], ah, bh[ni2]);
                    MMA_F16(acc[mi][ni2 * 2 + 1], ah, bh[ni2] + 2);
                }
            }
        }
        __syncthreads();
    }

    const int rbase = bm + wm * 64 + (lane >> 2);
    const int cbase = bn + wn * 32 + (lane & 3) * 2;
#pragma unroll
    for (int mi = 0; mi < 4; mi++) {
#pragma unroll
        for (int ni = 0; ni < 4; ni++) {
            const int col = cbase + ni * 8;
            const float2 b2v = *(const float2*)(bias + col);
#pragma unroll
            for (int half = 0; half < 2; half++) {
                const int row = rbase + mi * 16 + half * 8;
                *(float2*)(Cout + (size_t)row * HIDq + col) =
                    make_float2(acc[mi][ni][half * 2 + 0] + b2v.x,
                                acc[mi][ni][half * 2 + 1] + b2v.y);
            }
        }
    }
}

// ===========================================================================
// fp16 flash attention (R10 structure): 256 threads = 8 warps, warp owns 16
// query rows; 128-query tile, 64-key stages (2-stage). K and V fragments via
// x4 ldmatrix (two tiles per instruction). smem 55 KB, 2 CTAs/SM.
// ctx -> fp16 into g_xh [B*S, HID].
// ===========================================================================
#define QTILE  18432                    // 128 rows x 144 B
#define KVTILE 9216                     // 64 rows x 144 B
#define KVSTG  (2 * KVTILE)             // Kh, Vh
#define KVOFF  QTILE
#define ASMEM  (KVOFF + 2 * KVSTG)      // 55296
#define NTK    (Sq / 64)                // 16

__global__ __launch_bounds__(256, 2) void attn_mma_kernel(const float* __restrict__ mask)
{
    extern __shared__ char sm[];
    const uint32_t sb = smem_to_u32(sm);

    const int bh = blockIdx.y;
    const int b = bh >> 4, h = bh & 15;
    const int qbase = blockIdx.x * 128;
    const int tid = threadIdx.x, lane = tid & 31, wid = tid >> 5;
    const int wrow = wid * 16;

    const size_t hb = (size_t)bh * Sq * HDq;
    const __half* Qg = g_qh + hb;
    const __half* KVg[2] = {g_kh + hb, g_vh + hb};

#pragma unroll
    for (int t = 0; t < 4; t++) {
        const int id = t * 256 + tid;
        const int row = id >> 3, seg = id & 7;
        CP_ASYNC16(sb + (uint32_t)row * 144 + seg * 16,
                   Qg + (size_t)(qbase + row) * HDq + seg * 8);
    }

    auto issue_kv = [&](int kt) {
        const uint32_t base = sb + KVOFF + (uint32_t)(kt & 1) * KVSTG;
#pragma unroll
        for (int t = 0; t < 4; t++) {
            const int which = t >> 1;
            const int id = (t & 1) * 256 + tid;
            const int row = id >> 3, seg = id & 7;
            CP_ASYNC16(base + (uint32_t)which * KVTILE + (uint32_t)row * 144 + seg * 16,
                       KVg[which] + (size_t)(kt * 64 + row) * HDq + seg * 8);
        }
        CP_COMMIT();
    };

    issue_kv(0);

    float m_st[2] = {-1e30f, -1e30f};
    float l_st[2] = {0.f, 0.f};
    float ctx[8][4];
#pragma unroll
    for (int n = 0; n < 8; n++)
#pragma unroll
        for (int r = 0; r < 4; r++) ctx[n][r] = 0.f;

    const int r0 = qbase + wrow + (lane >> 2);

    // x4 K-frag: row = n2*16 + (lane&7) + ((lane>>4)&1)*8, k-half=(lane>>3)&1
    const uint32_t krow = (uint32_t)((lane & 7) + ((lane >> 4) & 1) * 8);
    const uint32_t kkp  = (uint32_t)(((lane >> 3) & 1) * 8) * 2;
    // x4 trans V-frag: rows kk2*16+(lane&15), col byte = (n2*2+((lane>>4)&1))*16
    const uint32_t vrow = (uint32_t)(lane & 15);
    const uint32_t vcol = (uint32_t)((lane >> 4) & 1) * 16;

    for (int kt = 0; kt < NTK; kt++) {
        if (kt + 1 < NTK) { issue_kv(kt + 1); CP_WAIT(1); }
        else              { CP_WAIT(0); }
        __syncthreads();

        const uint32_t kvb = sb + KVOFF + (uint32_t)(kt & 1) * KVSTG;

        float accs[8][4];
#pragma unroll
        for (int n = 0; n < 8; n++)
#pragma unroll
            for (int r = 0; r < 4; r++) accs[n][r] = 0.f;

#pragma unroll
        for (int k0 = 0; k0 < 64; k0 += 16) {
            uint32_t ah[4];
            const uint32_t aaddr = sb + (uint32_t)(wrow + (lane & 15)) * 144
                                 + (uint32_t)(k0 + (lane >> 4) * 8) * 2;
            LDMX4(ah, aaddr);
#pragma unroll
            for (int n2 = 0; n2 < 4; n2++) {
                const uint32_t baddr = kvb + (krow + (uint32_t)n2 * 16) * 144
                                     + (uint32_t)k0 * 2 + kkp;
                uint32_t kb[4];
                LDMX4(kb, baddr);
                MMA_F16(accs[n2 * 2 + 0], ah, kb);
                MMA_F16(accs[n2 * 2 + 1], ah, kb + 2);
            }
        }

        const float* mrow0 = mask + ((size_t)b * Sq + r0) * Sq + kt * 64 + (lane & 3) * 2;
        const float* mrow1 = mrow0 + 8 * Sq;
#pragma unroll
        for (int n = 0; n < 8; n++) {
            const float2 m0 = *(const float2*)(mrow0 + n * 8);
            const float2 m1 = *(const float2*)(mrow1 + n * 8);
            accs[n][0] = fmaf(m0.x, -1e9f, accs[n][0]);
            accs[n][1] = fmaf(m0.y, -1e9f, accs[n][1]);
            accs[n][2] = fmaf(m1.x, -1e9f, accs[n][2]);
            accs[n][3] = fmaf(m1.y, -1e9f, accs[n][3]);
        }

        float mx0 = -1e30f, mx1 = -1e30f;
#pragma unroll
        for (int n = 0; n < 8; n++) {
            mx0 = fmaxf(mx0, fmaxf(accs[n][0], accs[n][1]));
            mx1 = fmaxf(mx1, fmaxf(accs[n][2], accs[n][3]));
        }
        mx0 = fmaxf(mx0, __shfl_xor_sync(0xffffffffu, mx0, 1));
        mx0 = fmaxf(mx0, __shfl_xor_sync(0xffffffffu, mx0, 2));
        mx1 = fmaxf(mx1, __shfl_xor_sync(0xffffffffu, mx1, 1));
        mx1 = fmaxf(mx1, __shfl_xor_sync(0xffffffffu, mx1, 2));

        const float mn0 = fmaxf(m_st[0], mx0);
        const float mn1 = fmaxf(m_st[1], mx1);
        const float al0 = __expf(m_st[0] - mn0);
        const float al1 = __expf(m_st[1] - mn1);
        m_st[0] = mn0; m_st[1] = mn1;

        float sum0 = 0.f, sum1 = 0.f;
#pragma unroll
        for (int n = 0; n < 8; n++) {
            accs[n][0] = __expf(accs[n][0] - mn0);
            accs[n][1] = __expf(accs[n][1] - mn0);
            accs[n][2] = __expf(accs[n][2] - mn1);
            accs[n][3] = __expf(accs[n][3] - mn1);
            sum0 += accs[n][0] + accs[n][1];
            sum1 += accs[n][2] + accs[n][3];
        }
        sum0 += __shfl_xor_sync(0xffffffffu, sum0, 1);
        sum0 += __shfl_xor_sync(0xffffffffu, sum0, 2);
        sum1 += __shfl_xor_sync(0xffffffffu, sum1, 1);
        sum1 += __shfl_xor_sync(0xffffffffu, sum1, 2);
        l_st[0] = l_st[0] * al0 + sum0;
        l_st[1] = l_st[1] * al1 + sum1;

#pragma unroll
        for (int n = 0; n < 8; n++) {
            ctx[n][0] *= al0; ctx[n][1] *= al0;
            ctx[n][2] *= al1; ctx[n][3] *= al1;
        }

        const uint32_t vbase = kvb + KVTILE;
#pragma unroll
        for (int kk2 = 0; kk2 < 4; kk2++) {
            uint32_t pf[4];
            __half2 p0 = __floats2half2_rn(accs[2 * kk2][0],     accs[2 * kk2][1]);
            __half2 p1 = __floats2half2_rn(accs[2 * kk2][2],     accs[2 * kk2][3]);
            __half2 p2 = __floats2half2_rn(accs[2 * kk2 + 1][0], accs[2 * kk2 + 1][1]);
            __half2 p3 = __floats2half2_rn(accs[2 * kk2 + 1][2], accs[2 * kk2 + 1][3]);
            pf[0] = *(uint32_t*)&p0; pf[1] = *(uint32_t*)&p1;
            pf[2] = *(uint32_t*)&p2; pf[3] = *(uint32_t*)&p3;
#pragma unroll
            for (int n2 = 0; n2 < 4; n2++) {
                const uint32_t vaddr = vbase + (uint32_t)(kk2 * 16 + vrow) * 144
                                     + (uint32_t)n2 * 32 + vcol;
                uint32_t vh[4];
                LDMX4T(vh, vaddr);
                MMA_F16(ctx[n2 * 2 + 0], pf, vh);
                MMA_F16(ctx[n2 * 2 + 1], pf, vh + 2);
            }
        }
        __syncthreads();
    }

    const float inv0 = 1.0f / l_st[0];
    const float inv1 = 1.0f / l_st[1];
    const int cb = h * HDq + (lane & 3) * 2;
#pragma unroll
    for (int n = 0; n < 8; n++) {
        const int col = cb + n * 8;
        const size_t off0 = ((size_t)(b * Sq + r0)) * HIDq + col;
        const size_t off1 = ((size_t)(b * Sq + r0 + 8)) * HIDq + col;
        __half2 h0 = __floats2half2_rn(ctx[n][0] * inv0, ctx[n][1] * inv0);
        __half2 h1 = __floats2half2_rn(ctx[n][2] * inv1, ctx[n][3] * inv1);
        *(uint32_t*)(g_xh + off0) = *(uint32_t*)&h0;
        *(uint32_t*)(g_xh + off1) = *(uint32_t*)&h1;
    }
}

// ---------------------------------------------------------------------------
extern "C" void kernel_launch(void* const* d_in, const int* in_sizes, int n_in,
                              void* d_out, int out_size)
{
    (void)in_sizes; (void)n_in; (void)out_size;
    const float* x   = (const float*)d_in[0];
    const float* msk = (const float*)d_in[1];
    const float* Wq  = (const float*)d_in[2];
    const float* bq  = (const float*)d_in[3];
    const float* Wk  = (const float*)d_in[4];
    const float* bk  = (const float*)d_in[5];
    const float* Wv  = (const float*)d_in[6];
    const float* bv  = (const float*)d_in[7];
    const float* Wp  = (const float*)d_in[8];
    const float* bp  = (const float*)d_in[9];
    float* out = (float*)d_out;

    cudaFuncSetAttribute(gemm_qkv_kernel, cudaFuncAttributeMaxDynamicSharedMemorySize, GSMEM);
    cudaFuncSetAttribute(gemm_out_kernel, cudaFuncAttributeMaxDynamicSharedMemorySize, GSMEM);
    cudaFuncSetAttribute(attn_mma_kernel, cudaFuncAttributeMaxDynamicSharedMemorySize, ASMEM);

    convert_x_kernel<<<(Mq * HIDq) / (256 * 8), 256>>>(x);
    convw_all_kernel<<<dim3(32, 32, 4), 256>>>(Wq, Wk, Wv, Wp);

    gemm_qkv_kernel<<<dim3(HIDq / 128, Mq / 128, 3), 256, GSMEM>>>(bq, bk, bv);

    attn_mma_kernel<<<dim3(Sq / 128, Bq * NHq), 256, ASMEM>>>(msk);

    gemm_out_kernel<<<dim3(HIDq / 128, Mq / 128), 256, GSMEM>>>(bp, out);
}